// round 1
// baseline (speedup 1.0000x reference)
#include <cuda_runtime.h>

#define BB 64
#define LL 2048
#define DD 128
#define HH 4
#define AA 128
#define MM 16
#define VV 100000
#define HDIM 32

// ---------------- scratch (static device globals; no allocation) ----------------
__device__ float  g_pT[VV * MM];        // sigmoid(phi) transposed to [V][16]
__device__ float  g_PhiQ[BB * AA];
__device__ double g_sumpS[BB * MM];
__device__ float  g_PhiP[MM * AA];
__device__ double g_sizeP[MM];
__device__ float  g_AQ[BB * AA];
__device__ float  g_BP[MM * AA];
__device__ float  g_Vp[MM * HDIM];
__device__ float  g_C[BB * HH * DD];
__device__ int    g_is64;

__device__ __forceinline__ long long load_ll(const void* p, long long i, int is64) {
    return is64 ? ((const long long*)p)[i] : (long long)((const int*)p)[i];
}

// ---------------- K0: zero accumulators + detect index width ----------------
__global__ void k_init(const void* __restrict__ ids) {
    int tid = blockIdx.x * blockDim.x + threadIdx.x;
    int nt  = gridDim.x * blockDim.x;
    if (tid == 0) {
        // int64 little-endian with values < 2^31 -> every odd int32 word is 0
        const int* w = (const int*)ids;
        g_is64 = (w[1] == 0 && w[3] == 0 && w[5] == 0 && w[7] == 0) ? 1 : 0;
    }
    for (int i = tid; i < BB * AA; i += nt) g_PhiQ[i] = 0.f;
    for (int i = tid; i < BB * MM; i += nt) g_sumpS[i] = 0.0;
    for (int i = tid; i < MM * AA; i += nt) g_PhiP[i] = 0.f;
    for (int i = tid; i < MM;      i += nt) g_sizeP[i] = 0.0;
}

// ---------------- K1: pT = sigmoid(phi)^T, PhiP = p @ atom_emb, sizeP ----------------
// 256 threads. Chunk of 64 vocab entries at a time.
// Thread owns column a = tid&127 and 8 prototypes m0..m0+7 (m0 = (tid>>7)*8).
__global__ void k_proto(const float* __restrict__ phi, const float* __restrict__ emb) {
    __shared__ float p_sh[64 * 17];     // [vi][m], padded
    const int tid = threadIdx.x;
    const int a   = tid & 127;
    const int m0  = (tid >> 7) << 3;
    float  acc[8]  = {0, 0, 0, 0, 0, 0, 0, 0};
    double sacc[8] = {0, 0, 0, 0, 0, 0, 0, 0};
    const int nch = (VV + 63) >> 6;     // 1563

    for (int ch = blockIdx.x; ch < nch; ch += gridDim.x) {
        const int v0 = ch << 6;
        // load + sigmoid: coalesced over v within each prototype row
        for (int j = tid; j < 1024; j += 256) {
            int m = j >> 6, vi = j & 63, v = v0 + vi;
            float p = 0.f;
            if (v < VV) { float x = phi[m * VV + v]; p = 1.f / (1.f + expf(-x)); }
            p_sh[vi * 17 + m] = p;
        }
        __syncthreads();
        // transposed write of pT (coalesced 64B groups)
        for (int j = tid; j < 1024; j += 256) {
            int vi = j >> 4, m = j & 15, v = v0 + vi;
            if (v < VV) g_pT[v * 16 + m] = p_sh[vi * 17 + m];
        }
        // rank-1 accumulation into PhiP partials
        const int nv = (VV - v0 < 64) ? (VV - v0) : 64;
        for (int vi = 0; vi < nv; vi++) {
            float e = __ldg(&emb[(v0 + vi) * 128 + a]);
            #pragma unroll
            for (int mi = 0; mi < 8; mi++) {
                float pv = p_sh[vi * 17 + m0 + mi];
                acc[mi] += pv * e;
                if (a == 0) sacc[mi] += (double)pv;
            }
        }
        __syncthreads();
    }
    #pragma unroll
    for (int mi = 0; mi < 8; mi++) {
        atomicAdd(&g_PhiP[(m0 + mi) * 128 + a], acc[mi]);
        if (a == 0) atomicAdd(&g_sizeP[m0 + mi], sacc[mi]);
    }
}

// ---------------- K2: segment gather: PhiQ[b,:] and sum_p_S[b,m] ----------------
// grid = B * 16 splits; 8 warps/block; warp-register accumulation, 1 atomic flush.
__global__ void k_gather(const void* __restrict__ ids, const void* __restrict__ offs,
                         const float* __restrict__ emb) {
    const int is64 = g_is64;
    const int b = blockIdx.x >> 4;
    const int s = blockIdx.x & 15;
    const long long start = load_ll(offs, b,     is64);
    const long long end   = load_ll(offs, b + 1, is64);
    const long long len   = end - start;
    const long long chunk = (len + 15) >> 4;
    const long long cs = start + (long long)s * chunk;
    long long ce = cs + chunk; if (ce > end) ce = end;

    const int w = threadIdx.x >> 5, lane = threadIdx.x & 31;
    const float4* emb4 = (const float4*)emb;
    float4 aq = make_float4(0.f, 0.f, 0.f, 0.f);
    double as = 0.0;

    long long i = cs + w;
    for (; i + 8 < ce; i += 16) {               // 2x unroll for MLP
        int id0 = (int)load_ll(ids, i,     is64);
        int id1 = (int)load_ll(ids, i + 8, is64);
        float4 e0 = __ldg(&emb4[id0 * 32 + lane]);
        float4 e1 = __ldg(&emb4[id1 * 32 + lane]);
        float p0 = 0.f, p1 = 0.f;
        if (lane < 16) { p0 = __ldg(&g_pT[id0 * 16 + lane]); p1 = __ldg(&g_pT[id1 * 16 + lane]); }
        aq.x += e0.x + e1.x; aq.y += e0.y + e1.y;
        aq.z += e0.z + e1.z; aq.w += e0.w + e1.w;
        as += (double)p0 + (double)p1;
    }
    for (; i < ce; i += 8) {
        int id = (int)load_ll(ids, i, is64);
        float4 e = __ldg(&emb4[id * 32 + lane]);
        aq.x += e.x; aq.y += e.y; aq.z += e.z; aq.w += e.w;
        if (lane < 16) as += (double)__ldg(&g_pT[id * 16 + lane]);
    }
    float* dst = &g_PhiQ[b * 128 + lane * 4];
    atomicAdd(dst + 0, aq.x); atomicAdd(dst + 1, aq.y);
    atomicAdd(dst + 2, aq.z); atomicAdd(dst + 3, aq.w);
    if (lane < 16) atomicAdd(&g_sumpS[b * 16 + lane], as);
}

// ---------------- K3a: AQ = PhiQ @ W_A^T ; BP = PhiP @ W_B^T ; Vp = PhiP @ W_val^T + b_val ----------------
__global__ void k_proj(const float* __restrict__ W_A, const float* __restrict__ W_B,
                       const float* __restrict__ W_val, const float* __restrict__ b_val) {
    __shared__ float xs[128];
    const int tid = threadIdx.x;
    if (blockIdx.x < 64) {
        const int b = blockIdx.x;
        xs[tid] = g_PhiQ[b * 128 + tid];
        __syncthreads();
        float acc = 0.f;
        #pragma unroll 8
        for (int k = 0; k < 128; k++) acc += xs[k] * W_A[tid * 128 + k];
        g_AQ[b * 128 + tid] = acc;
    } else {
        const int m = blockIdx.x - 64;
        xs[tid] = g_PhiP[m * 128 + tid];
        __syncthreads();
        float acc = 0.f;
        #pragma unroll 8
        for (int k = 0; k < 128; k++) acc += xs[k] * W_B[tid * 128 + k];
        g_BP[m * 128 + tid] = acc;
        if (tid < 32) {
            float av = b_val[tid];
            #pragma unroll 8
            for (int k = 0; k < 128; k++) av += xs[k] * W_val[tid * 128 + k];
            g_Vp[m * 32 + tid] = av;
        }
    }
}

// ---------------- K3b: scores -> softmax -> Z -> C[b,h,j] ----------------
__global__ void k_attn(const void* __restrict__ offs, const float* __restrict__ size_w,
                       const float* __restrict__ W_out) {
    __shared__ float Zs[32];
    const int b = blockIdx.x;
    const int tid = threadIdx.x;
    if (tid < 32) {
        const int lane = tid;
        const int is64 = g_is64;
        const float sizeQ = (float)(load_ll(offs, b + 1, is64) - load_ll(offs, b, is64));
        const float sw0 = size_w[0], sw1 = size_w[1];
        float s[16];
        #pragma unroll
        for (int m = 0; m < 16; m++) {
            float part = 0.f;
            #pragma unroll
            for (int a = lane; a < 128; a += 32) part += g_AQ[b * 128 + a] * g_BP[m * 128 + a];
            #pragma unroll
            for (int off = 16; off; off >>= 1) part += __shfl_xor_sync(0xffffffffu, part, off);
            double sizeP = g_sizeP[m];
            double sump  = g_sumpS[b * 16 + m];
            double delta = (double)sizeQ + sizeP - 2.0 * sump;
            s[m] = (float)(-0.3 * delta + (double)part
                           + (double)sw0 * (double)sizeQ + (double)sw1 * sizeP);
        }
        float mx = s[0];
        #pragma unroll
        for (int m = 1; m < 16; m++) mx = fmaxf(mx, s[m]);
        float sum = 0.f;
        #pragma unroll
        for (int m = 0; m < 16; m++) { s[m] = expf(s[m] - mx); sum += s[m]; }
        const float inv = 1.f / sum;
        float z = 0.f;
        #pragma unroll
        for (int m = 0; m < 16; m++) z += s[m] * inv * g_Vp[m * 32 + lane];
        Zs[lane] = z;
    }
    __syncthreads();
    const int j = tid;
    #pragma unroll
    for (int h = 0; h < 4; h++) {
        float acc = 0.f;
        #pragma unroll
        for (int d = 0; d < 32; d++) acc += Zs[d] * W_out[j * 128 + h * 32 + d];
        g_C[b * 512 + h * 128 + j] = acc;
    }
}

// ---------------- K4: per-token gates + output (one warp per token) ----------------
__global__ __launch_bounds__(256) void k_tokens(const float* __restrict__ ts,
        const float* __restrict__ W_gate, const float* __restrict__ b_gate,
        const float* __restrict__ b_out, float* __restrict__ out) {
    __shared__ float wg[512];
    __shared__ float bo[128];
    __shared__ float bg[4];
    const int tid = threadIdx.x;
    wg[tid] = W_gate[tid];
    wg[tid + 256] = W_gate[tid + 256];
    if (tid < 128) bo[tid] = b_out[tid];
    if (tid < 4)   bg[tid] = b_gate[tid];
    __syncthreads();

    const int w = tid >> 5, lane = tid & 31;
    const int token = blockIdx.x * 8 + w;
    const int b = token >> 11;                       // L = 2048
    const float4* ts4 = (const float4*)ts;
    const float4 x = __ldg(&ts4[(long long)token * 32 + lane]);

    float g[4];
    const float4* wg4 = (const float4*)wg;
    #pragma unroll
    for (int h = 0; h < 4; h++) {
        float4 wv = wg4[h * 32 + lane];
        g[h] = x.x * wv.x + x.y * wv.y + x.z * wv.z + x.w * wv.w;
    }
    #pragma unroll
    for (int off = 16; off; off >>= 1) {
        #pragma unroll
        for (int h = 0; h < 4; h++) g[h] += __shfl_xor_sync(0xffffffffu, g[h], off);
    }
    #pragma unroll
    for (int h = 0; h < 4; h++) g[h] += bg[h];
    float mx = fmaxf(fmaxf(g[0], g[1]), fmaxf(g[2], g[3]));
    float sum = 0.f;
    #pragma unroll
    for (int h = 0; h < 4; h++) { g[h] = expf(g[h] - mx); sum += g[h]; }
    const float inv = 1.f / sum;

    const float4* C4 = (const float4*)(g_C + b * 512);
    float4 o = ((const float4*)bo)[lane];
    #pragma unroll
    for (int h = 0; h < 4; h++) {
        float4 c = __ldg(&C4[h * 32 + lane]);
        float gh = g[h] * inv;
        o.x += gh * c.x; o.y += gh * c.y; o.z += gh * c.z; o.w += gh * c.w;
    }
    ((float4*)out)[(long long)token * 32 + lane] = o;
}

// ---------------- launch ----------------
extern "C" void kernel_launch(void* const* d_in, const int* in_sizes, int n_in,
                              void* d_out, int out_size) {
    const float* ts    = (const float*)d_in[0];
    const void*  ids   = d_in[1];
    const void*  offs  = d_in[2];
    const float* emb   = (const float*)d_in[3];
    const float* phi   = (const float*)d_in[4];
    const float* W_A   = (const float*)d_in[5];
    const float* W_B   = (const float*)d_in[6];
    const float* W_val = (const float*)d_in[7];
    const float* b_val = (const float*)d_in[8];
    const float* W_g   = (const float*)d_in[9];
    const float* b_g   = (const float*)d_in[10];
    const float* W_o   = (const float*)d_in[11];
    const float* b_o   = (const float*)d_in[12];
    const float* szw   = (const float*)d_in[13];

    k_init  <<<32,    256>>>(ids);
    k_proto <<<296,   256>>>(phi, emb);
    k_gather<<<BB * 16, 256>>>(ids, offs, emb);
    k_proj  <<<80,    128>>>(W_A, W_B, W_val, b_val);
    k_attn  <<<64,    128>>>(offs, szw, W_o);
    k_tokens<<<(BB * LL) / 8, 256>>>(ts, W_g, b_g, b_o, (float*)d_out);
}

// round 2
// speedup vs baseline: 9.6031x; 9.6031x over previous
#include <cuda_runtime.h>

#define BB 64
#define LL 2048
#define DD 128
#define HH 4
#define AA 128
#define MM 16
#define VV 100000
#define HDIM 32

// ---------------- scratch (static device globals; no allocation) ----------------
__device__ float  g_pT[VV * MM];        // sigmoid(phi) transposed to [V][16]
__device__ float  g_PhiQ[BB * AA];
__device__ double g_sumpS[BB * MM];
__device__ float  g_PhiPt[AA * MM];     // PhiP transposed: [a][m]
__device__ double g_sizeP[MM];
__device__ float  g_AQ[BB * AA];
__device__ float  g_BP[MM * AA];
__device__ float  g_Vp[MM * HDIM];
__device__ float  g_C[BB * HH * DD];
__device__ int    g_is64;

__device__ __forceinline__ long long load_ll(const void* p, long long i, int is64) {
    return is64 ? ((const long long*)p)[i] : (long long)((const int*)p)[i];
}

__device__ __forceinline__ void red_add_v4(float* p, float4 v) {
    asm volatile("red.global.add.v4.f32 [%0], {%1,%2,%3,%4};"
                 :: "l"(p), "f"(v.x), "f"(v.y), "f"(v.z), "f"(v.w) : "memory");
}

// ---------------- K0: zero accumulators + detect index width ----------------
__global__ void k_init(const void* __restrict__ ids) {
    int tid = blockIdx.x * blockDim.x + threadIdx.x;
    int nt  = gridDim.x * blockDim.x;
    if (tid == 0) {
        const int* w = (const int*)ids;
        g_is64 = (w[1] == 0 && w[3] == 0 && w[5] == 0 && w[7] == 0) ? 1 : 0;
    }
    for (int i = tid; i < BB * AA; i += nt) g_PhiQ[i] = 0.f;
    for (int i = tid; i < BB * MM; i += nt) g_sumpS[i] = 0.0;
    for (int i = tid; i < AA * MM; i += nt) g_PhiPt[i] = 0.f;
    for (int i = tid; i < MM;      i += nt) g_sizeP[i] = 0.0;
}

// ---------------- K1: pT = sigmoid(phi)^T, PhiPt += p @ emb, sizeP ----------------
// One block per 256-vocab slab. 391 blocks x 256 threads.
__global__ __launch_bounds__(256) void k_proto(const float* __restrict__ phi,
                                               const float* __restrict__ emb) {
    __shared__ float  p_sh[256 * 20];   // [v][m] padded to 20 (float4-aligned)
    __shared__ double sd[16 * 8];
    const int tid  = threadIdx.x;
    const int lane = tid & 31;
    const int wrp  = tid >> 5;
    const int v0   = blockIdx.x << 8;
    const int nv   = (VV - v0 < 256) ? (VV - v0) : 256;

    // Phase A: sigmoid + stage to shared; per-m sizeP partials (double)
    #pragma unroll
    for (int m = 0; m < 16; m++) {
        float p = 0.f;
        if (tid < nv) { float x = phi[m * VV + v0 + tid]; p = 1.f / (1.f + expf(-x)); }
        p_sh[tid * 20 + m] = p;
        double d = (double)p;
        #pragma unroll
        for (int off = 16; off; off >>= 1) d += __shfl_xor_sync(0xffffffffu, d, off);
        if (lane == 0) sd[m * 8 + wrp] = d;
    }
    __syncthreads();
    if (tid < 16) {
        double s = 0.0;
        #pragma unroll
        for (int w = 0; w < 8; w++) s += sd[tid * 8 + w];
        atomicAdd(&g_sizeP[tid], s);
    }
    // pT write (coalesced: linear in j)
    for (int j = tid; j < nv * 16; j += 256)
        g_pT[v0 * 16 + j] = p_sh[(j >> 4) * 20 + (j & 15)];

    // Phase B: rank-update PhiPt. Thread owns column a, vi-parallel x2.
    const int a = tid & 127;
    const int g = tid >> 7;
    float acc[16];
    #pragma unroll
    for (int i = 0; i < 16; i++) acc[i] = 0.f;
    const float4* p4 = (const float4*)p_sh;
    #pragma unroll 4
    for (int vi = g; vi < nv; vi += 2) {
        float e = __ldg(&emb[(v0 + vi) * 128 + a]);
        float4 pA = p4[vi * 5 + 0], pB = p4[vi * 5 + 1];
        float4 pC = p4[vi * 5 + 2], pD = p4[vi * 5 + 3];
        acc[0]  += pA.x * e; acc[1]  += pA.y * e; acc[2]  += pA.z * e; acc[3]  += pA.w * e;
        acc[4]  += pB.x * e; acc[5]  += pB.y * e; acc[6]  += pB.z * e; acc[7]  += pB.w * e;
        acc[8]  += pC.x * e; acc[9]  += pC.y * e; acc[10] += pC.z * e; acc[11] += pC.w * e;
        acc[12] += pD.x * e; acc[13] += pD.y * e; acc[14] += pD.z * e; acc[15] += pD.w * e;
    }
    __syncthreads();
    // combine the two vi-groups via shared (reuse p_sh), layout [m][a] (conflict-free)
    float* red = p_sh;
    if (g == 1) {
        #pragma unroll
        for (int mi = 0; mi < 16; mi++) red[mi * 128 + a] = acc[mi];
    }
    __syncthreads();
    if (g == 0) {
        #pragma unroll
        for (int mi = 0; mi < 16; mi++) acc[mi] += red[mi * 128 + a];
        float* dst = &g_PhiPt[a * 16];
        red_add_v4(dst + 0,  make_float4(acc[0],  acc[1],  acc[2],  acc[3]));
        red_add_v4(dst + 4,  make_float4(acc[4],  acc[5],  acc[6],  acc[7]));
        red_add_v4(dst + 8,  make_float4(acc[8],  acc[9],  acc[10], acc[11]));
        red_add_v4(dst + 12, make_float4(acc[12], acc[13], acc[14], acc[15]));
    }
}

// ---------------- K2: segment gather: PhiQ[b,:] and sum_p_S[b,m] ----------------
// grid = B * 64 splits; 8 warps/block; block-level reduction, vector red flush.
__global__ __launch_bounds__(256) void k_gather(const void* __restrict__ ids,
                                                const void* __restrict__ offs,
                                                const float* __restrict__ emb) {
    __shared__ float  sred[8 * 136];
    __shared__ double sdd[8 * 17];
    const int is64 = g_is64;
    const int b = blockIdx.x >> 6;
    const int s = blockIdx.x & 63;
    const long long start = load_ll(offs, b,     is64);
    const long long end   = load_ll(offs, b + 1, is64);
    const long long len   = end - start;
    const long long chunk = (len + 63) >> 6;
    const long long cs = start + (long long)s * chunk;
    long long ce = cs + chunk; if (ce > end) ce = end;

    const int w = threadIdx.x >> 5, lane = threadIdx.x & 31;
    const float4* emb4 = (const float4*)emb;
    float4 aq = make_float4(0.f, 0.f, 0.f, 0.f);
    double as = 0.0;

    long long i = cs + w;
    for (; i + 8 < ce; i += 16) {
        int id0 = (int)load_ll(ids, i,     is64);
        int id1 = (int)load_ll(ids, i + 8, is64);
        float4 e0 = __ldg(&emb4[id0 * 32 + lane]);
        float4 e1 = __ldg(&emb4[id1 * 32 + lane]);
        float p0 = 0.f, p1 = 0.f;
        if (lane < 16) { p0 = __ldg(&g_pT[id0 * 16 + lane]); p1 = __ldg(&g_pT[id1 * 16 + lane]); }
        aq.x += e0.x + e1.x; aq.y += e0.y + e1.y;
        aq.z += e0.z + e1.z; aq.w += e0.w + e1.w;
        as += (double)p0 + (double)p1;
    }
    for (; i < ce; i += 8) {
        int id = (int)load_ll(ids, i, is64);
        float4 e = __ldg(&emb4[id * 32 + lane]);
        aq.x += e.x; aq.y += e.y; aq.z += e.z; aq.w += e.w;
        if (lane < 16) as += (double)__ldg(&g_pT[id * 16 + lane]);
    }
    // per-warp stage
    ((float4*)(sred + w * 136))[lane] = aq;
    if (lane < 16) sdd[w * 17 + lane] = as;
    __syncthreads();
    if (threadIdx.x < 128) {
        float t = 0.f;
        #pragma unroll
        for (int w2 = 0; w2 < 8; w2++) t += sred[w2 * 136 + threadIdx.x];
        sred[threadIdx.x] = t;          // each thread touches only its own index
    }
    if (threadIdx.x < 16) {
        double td = 0.0;
        #pragma unroll
        for (int w2 = 0; w2 < 8; w2++) td += sdd[w2 * 17 + threadIdx.x];
        atomicAdd(&g_sumpS[b * 16 + threadIdx.x], td);
    }
    __syncthreads();
    if (threadIdx.x < 32) {
        float4 v = ((float4*)sred)[threadIdx.x];
        red_add_v4(&g_PhiQ[b * 128 + threadIdx.x * 4], v);
    }
}

// ---------------- K3a: AQ = PhiQ @ W_A^T ; BP = PhiP @ W_B^T ; Vp = PhiP @ W_val^T + b_val
__global__ void k_proj(const float* __restrict__ W_A, const float* __restrict__ W_B,
                       const float* __restrict__ W_val, const float* __restrict__ b_val) {
    __shared__ float xs[128];
    const int tid = threadIdx.x;
    if (blockIdx.x < 64) {
        const int b = blockIdx.x;
        xs[tid] = g_PhiQ[b * 128 + tid];
        __syncthreads();
        const float4* W4 = (const float4*)(W_A + tid * 128);
        float acc = 0.f;
        #pragma unroll 8
        for (int k = 0; k < 32; k++) {
            float4 wv = __ldg(&W4[k]);
            acc += xs[k*4]*wv.x + xs[k*4+1]*wv.y + xs[k*4+2]*wv.z + xs[k*4+3]*wv.w;
        }
        g_AQ[b * 128 + tid] = acc;
    } else {
        const int m = blockIdx.x - 64;
        xs[tid] = g_PhiPt[tid * 16 + m];
        __syncthreads();
        const float4* W4 = (const float4*)(W_B + tid * 128);
        float acc = 0.f;
        #pragma unroll 8
        for (int k = 0; k < 32; k++) {
            float4 wv = __ldg(&W4[k]);
            acc += xs[k*4]*wv.x + xs[k*4+1]*wv.y + xs[k*4+2]*wv.z + xs[k*4+3]*wv.w;
        }
        g_BP[m * 128 + tid] = acc;
        if (tid < 32) {
            const float4* Wv4 = (const float4*)(W_val + tid * 128);
            float av = b_val[tid];
            #pragma unroll 8
            for (int k = 0; k < 32; k++) {
                float4 wv = __ldg(&Wv4[k]);
                av += xs[k*4]*wv.x + xs[k*4+1]*wv.y + xs[k*4+2]*wv.z + xs[k*4+3]*wv.w;
            }
            g_Vp[m * 32 + tid] = av;
        }
    }
}

// ---------------- K3b: scores -> softmax -> Z -> C[b,h,j] ----------------
__global__ void k_attn(const void* __restrict__ offs, const float* __restrict__ size_w,
                       const float* __restrict__ W_out) {
    __shared__ float Zs[32];
    const int b = blockIdx.x;
    const int tid = threadIdx.x;
    if (tid < 32) {
        const int lane = tid;
        const int is64 = g_is64;
        const float sizeQ = (float)(load_ll(offs, b + 1, is64) - load_ll(offs, b, is64));
        const float sw0 = size_w[0], sw1 = size_w[1];
        float s[16];
        #pragma unroll
        for (int m = 0; m < 16; m++) {
            float part = 0.f;
            #pragma unroll
            for (int a = lane; a < 128; a += 32) part += g_AQ[b * 128 + a] * g_BP[m * 128 + a];
            #pragma unroll
            for (int off = 16; off; off >>= 1) part += __shfl_xor_sync(0xffffffffu, part, off);
            double sizeP = g_sizeP[m];
            double sump  = g_sumpS[b * 16 + m];
            double delta = (double)sizeQ + sizeP - 2.0 * sump;
            s[m] = (float)(-0.3 * delta + (double)part
                           + (double)sw0 * (double)sizeQ + (double)sw1 * sizeP);
        }
        float mx = s[0];
        #pragma unroll
        for (int m = 1; m < 16; m++) mx = fmaxf(mx, s[m]);
        float sum = 0.f;
        #pragma unroll
        for (int m = 0; m < 16; m++) { s[m] = expf(s[m] - mx); sum += s[m]; }
        const float inv = 1.f / sum;
        float z = 0.f;
        #pragma unroll
        for (int m = 0; m < 16; m++) z += s[m] * inv * g_Vp[m * 32 + lane];
        Zs[lane] = z;
    }
    __syncthreads();
    const int j = tid;
    const float4* Wo4 = (const float4*)(W_out + j * 128);
    const float4* Z4  = (const float4*)Zs;
    #pragma unroll
    for (int h = 0; h < 4; h++) {
        float acc = 0.f;
        #pragma unroll
        for (int d = 0; d < 8; d++) {
            float4 wv = __ldg(&Wo4[h * 8 + d]);
            float4 zv = Z4[d];
            acc += zv.x*wv.x + zv.y*wv.y + zv.z*wv.z + zv.w*wv.w;
        }
        g_C[b * 512 + h * 128 + j] = acc;
    }
}

// ---------------- K4: per-token gates + output (one warp per token) ----------------
__global__ __launch_bounds__(256) void k_tokens(const float* __restrict__ ts,
        const float* __restrict__ W_gate, const float* __restrict__ b_gate,
        const float* __restrict__ b_out, float* __restrict__ out) {
    __shared__ float wg[512];
    __shared__ float bo[128];
    __shared__ float bg[4];
    const int tid = threadIdx.x;
    wg[tid] = W_gate[tid];
    wg[tid + 256] = W_gate[tid + 256];
    if (tid < 128) bo[tid] = b_out[tid];
    if (tid < 4)   bg[tid] = b_gate[tid];
    __syncthreads();

    const int w = tid >> 5, lane = tid & 31;
    const int token = blockIdx.x * 8 + w;
    const int b = token >> 11;                       // L = 2048
    const float4* ts4 = (const float4*)ts;
    const float4 x = __ldg(&ts4[(long long)token * 32 + lane]);

    float g[4];
    const float4* wg4 = (const float4*)wg;
    #pragma unroll
    for (int h = 0; h < 4; h++) {
        float4 wv = wg4[h * 32 + lane];
        g[h] = x.x * wv.x + x.y * wv.y + x.z * wv.z + x.w * wv.w;
    }
    #pragma unroll
    for (int off = 16; off; off >>= 1) {
        #pragma unroll
        for (int h = 0; h < 4; h++) g[h] += __shfl_xor_sync(0xffffffffu, g[h], off);
    }
    #pragma unroll
    for (int h = 0; h < 4; h++) g[h] += bg[h];
    float mx = fmaxf(fmaxf(g[0], g[1]), fmaxf(g[2], g[3]));
    float sum = 0.f;
    #pragma unroll
    for (int h = 0; h < 4; h++) { g[h] = expf(g[h] - mx); sum += g[h]; }
    const float inv = 1.f / sum;

    const float4* C4 = (const float4*)(g_C + b * 512);
    float4 o = ((const float4*)bo)[lane];
    #pragma unroll
    for (int h = 0; h < 4; h++) {
        float4 c = __ldg(&C4[h * 32 + lane]);
        float gh = g[h] * inv;
        o.x += gh * c.x; o.y += gh * c.y; o.z += gh * c.z; o.w += gh * c.w;
    }
    ((float4*)out)[(long long)token * 32 + lane] = o;
}

// ---------------- launch ----------------
extern "C" void kernel_launch(void* const* d_in, const int* in_sizes, int n_in,
                              void* d_out, int out_size) {
    const float* ts    = (const float*)d_in[0];
    const void*  ids   = d_in[1];
    const void*  offs  = d_in[2];
    const float* emb   = (const float*)d_in[3];
    const float* phi   = (const float*)d_in[4];
    const float* W_A   = (const float*)d_in[5];
    const float* W_B   = (const float*)d_in[6];
    const float* W_val = (const float*)d_in[7];
    const float* b_val = (const float*)d_in[8];
    const float* W_g   = (const float*)d_in[9];
    const float* b_g   = (const float*)d_in[10];
    const float* W_o   = (const float*)d_in[11];
    const float* b_o   = (const float*)d_in[12];
    const float* szw   = (const float*)d_in[13];

    k_init  <<<32,  256>>>(ids);
    k_proto <<<(VV + 255) / 256, 256>>>(phi, emb);
    k_gather<<<BB * 64, 256>>>(ids, offs, emb);
    k_proj  <<<80,  128>>>(W_A, W_B, W_val, b_val);
    k_attn  <<<64,  128>>>(offs, szw, W_o);
    k_tokens<<<(BB * LL) / 8, 256>>>(ts, W_g, b_g, b_o, (float*)d_out);
}